// round 4
// baseline (speedup 1.0000x reference)
#include <cuda_runtime.h>
#include <cuda_bf16.h>

#define BB 512
#define NN 512

// scratch: per-(batch,row) weight sums (1 MB, static device array — no alloc)
__device__ float g_wsum[BB * NN];

// ---------------------------------------------------------------------------
// Pass 1: w[b,i] = sum_{j != i} exp(-acos(clip(dot(n_i, n_j), -1, 1)))
// One block per batch; thread i owns row i; batch normals staged SoA in smem.
// ---------------------------------------------------------------------------
__global__ __launch_bounds__(NN) void pair_kernel(const float* __restrict__ normals) {
    __shared__ float sx[NN];
    __shared__ float sy[NN];
    __shared__ float sz[NN];

    const int b = blockIdx.x;
    const int i = threadIdx.x;
    const float* base = normals + (size_t)b * NN * 3;

    // AoS -> SoA shared stage (tiny: 6 KB)
    sx[i] = base[i * 3 + 0];
    sy[i] = base[i * 3 + 1];
    sz[i] = base[i * 3 + 2];
    __syncthreads();

    const float nx = sx[i];
    const float ny = sy[i];
    const float nz = sz[i];

    // 4 accumulators to break the add dependency chain
    float a0 = 0.f, a1 = 0.f, a2 = 0.f, a3 = 0.f;

    #pragma unroll 4
    for (int j = 0; j < NN; j += 4) {
        // all lanes read the same j -> smem broadcast, conflict-free
        #pragma unroll
        for (int u = 0; u < 4; u++) {
            const int jj = j + u;
            float x = fmaf(nx, sx[jj], fmaf(ny, sy[jj], nz * sz[jj]));
            x = fminf(1.0f, fmaxf(-1.0f, x));
            float w = __expf(-acosf(x));
            w = (jj == i) ? 0.0f : w;
            if (u == 0) a0 += w;
            else if (u == 1) a1 += w;
            else if (u == 2) a2 += w;
            else a3 += w;
        }
    }

    g_wsum[b * NN + i] = (a0 + a1) + (a2 + a3);
}

// ---------------------------------------------------------------------------
// Pass 2: out[b] = normalize( sum_i w[b,i] * n_i )
// (global max division cancels under normalization — skipped)
// ---------------------------------------------------------------------------
__global__ __launch_bounds__(NN) void reduce_kernel(const float* __restrict__ normals,
                                                    float* __restrict__ out) {
    const int b = blockIdx.x;
    const int i = threadIdx.x;
    const float* base = normals + (size_t)b * NN * 3;

    const float w = g_wsum[b * NN + i];
    float px = w * base[i * 3 + 0];
    float py = w * base[i * 3 + 1];
    float pz = w * base[i * 3 + 2];

    // warp reduce
    #pragma unroll
    for (int off = 16; off > 0; off >>= 1) {
        px += __shfl_down_sync(0xFFFFFFFFu, px, off);
        py += __shfl_down_sync(0xFFFFFFFFu, py, off);
        pz += __shfl_down_sync(0xFFFFFFFFu, pz, off);
    }

    __shared__ float rx[16], ry[16], rz[16];
    const int warp = i >> 5;
    const int lane = i & 31;
    if (lane == 0) {
        rx[warp] = px;
        ry[warp] = py;
        rz[warp] = pz;
    }
    __syncthreads();

    if (warp == 0) {
        float qx = (lane < 16) ? rx[lane] : 0.f;
        float qy = (lane < 16) ? ry[lane] : 0.f;
        float qz = (lane < 16) ? rz[lane] : 0.f;
        #pragma unroll
        for (int off = 8; off > 0; off >>= 1) {
            qx += __shfl_down_sync(0xFFFFFFFFu, qx, off);
            qy += __shfl_down_sync(0xFFFFFFFFu, qy, off);
            qz += __shfl_down_sync(0xFFFFFFFFu, qz, off);
        }
        if (lane == 0) {
            const float s2 = fmaf(qx, qx, fmaf(qy, qy, qz * qz));
            const float inv = rsqrtf(fmaxf(s2, 1e-20f));
            out[b * 3 + 0] = qx * inv;
            out[b * 3 + 1] = qy * inv;
            out[b * 3 + 2] = qz * inv;
        }
    }
}

extern "C" void kernel_launch(void* const* d_in, const int* in_sizes, int n_in,
                              void* d_out, int out_size) {
    const float* normals = (const float*)d_in[0];   // [512,512,3] f32
    // d_in[1] = weights — unused by the reference math
    float* out = (float*)d_out;                     // [512,3] f32

    pair_kernel<<<BB, NN>>>(normals);
    reduce_kernel<<<BB, NN>>>(normals, out);
}

// round 5
// speedup vs baseline: 1.6057x; 1.6057x over previous
#include <cuda_runtime.h>
#include <cuda_bf16.h>

#define BB 512
#define NN 512
#define TPB 256     // threads per pair-block; each thread owns rows tid and tid+256
#define JHALF 256   // j-iterations per block (j-range split across blockIdx.y)

typedef unsigned long long ull;

// scratch: two j-half partial sums per (batch,row) — deterministic (no atomics)
__device__ float g_wsum[2][BB * NN];

// ---- packed f32x2 helpers -------------------------------------------------
__device__ __forceinline__ ull pk(float lo, float hi) {
    ull r; asm("mov.b64 %0,{%1,%2};" : "=l"(r) : "f"(lo), "f"(hi)); return r;
}
__device__ __forceinline__ void upk(ull v, float& lo, float& hi) {
    asm("mov.b64 {%0,%1},%2;" : "=f"(lo), "=f"(hi) : "l"(v));
}
__device__ __forceinline__ ull fma2(ull a, ull b, ull c) {
    ull d; asm("fma.rn.f32x2 %0,%1,%2,%3;" : "=l"(d) : "l"(a), "l"(b), "l"(c)); return d;
}
__device__ __forceinline__ ull mul2(ull a, ull b) {
    ull d; asm("mul.rn.f32x2 %0,%1,%2;" : "=l"(d) : "l"(a), "l"(b)); return d;
}
__device__ __forceinline__ ull add2(ull a, ull b) {
    ull d; asm("add.rn.f32x2 %0,%1,%2;" : "=l"(d) : "l"(a), "l"(b)); return d;
}
__device__ __forceinline__ float sqrt_apx(float x) {
    float r; asm("sqrt.approx.f32 %0,%1;" : "=f"(r) : "f"(x)); return r;
}
__device__ __forceinline__ float ex2_apx(float x) {
    float r; asm("ex2.approx.f32 %0,%1;" : "=f"(r) : "f"(x)); return r;
}
__device__ __forceinline__ float sgn1(float x) {  // copysign(1.0f, x) as one LOP3
    return __uint_as_float((__float_as_uint(x) & 0x80000000u) | 0x3F800000u);
}

// ---- fused exp(-acos(x)) --------------------------------------------------
// acos(t) ~= sqrt(1-t) * P(t) on [0,1]  (A&S 4.4.46, |err| ~ 2e-8)
// coefficients pre-multiplied by -log2(e); reflection for x<0 via sign FMA:
//   e = sgn(x) * (s*C(|x|) + L*pi/2) - L*pi/2 ;  w = 2^e
#define KC0 (-2.2661800583f)
#define KC1 ( 0.3096006513f)
#define KC2 (-0.1283697188f)
#define KC3 ( 0.0723862201f)
#define KC4 (-0.0445675664f)
#define KC5 ( 0.0246529616f)
#define KC6 (-0.0096228849f)
#define KC7 ( 0.0018213895f)
#define KLPI2 ( 2.2661800709f)   //  (pi/2)*log2(e)

// scalar version (bit-identical op chain to the packed loop body) — self term
__device__ __forceinline__ float wfun(float x) {
    x = fminf(1.0f, fmaxf(-1.0f, x));
    float t = fabsf(x);
    float s = sqrt_apx(1.0f - t);
    float P = fmaf(KC7, t, KC6);
    P = fmaf(P, t, KC5);  P = fmaf(P, t, KC4);
    P = fmaf(P, t, KC3);  P = fmaf(P, t, KC2);
    P = fmaf(P, t, KC1);  P = fmaf(P, t, KC0);
    float r = fmaf(s, P, KLPI2);
    return ex2_apx(fmaf(sgn1(x), r, -KLPI2));
}

// ---------------------------------------------------------------------------
// Pass 1: partial row sums of w(i,j) over j in this block's half-range.
// grid (BB, 2); block TPB. Thread owns rows i0=tid, i1=tid+256 packed in f32x2.
// ---------------------------------------------------------------------------
__global__ __launch_bounds__(TPB) void pair_kernel(const float* __restrict__ normals) {
    __shared__ ull sdx[JHALF];
    __shared__ ull sdy[JHALF];
    __shared__ ull sdz[JHALF];

    const int b   = blockIdx.x;
    const int h   = blockIdx.y;          // which j-half
    const int tid = threadIdx.x;
    const float* base = normals + (size_t)b * NN * 3;

    // stage this half's j-normals, duplicated into both f32x2 halves
    {
        const int j = h * JHALF + tid;
        const float vx = base[j * 3 + 0];
        const float vy = base[j * 3 + 1];
        const float vz = base[j * 3 + 2];
        sdx[tid] = pk(vx, vx);
        sdy[tid] = pk(vy, vy);
        sdz[tid] = pk(vz, vz);
    }
    __syncthreads();

    const int i0 = tid;
    const int i1 = tid + TPB;
    const float ax = base[i0 * 3 + 0], aX = base[i1 * 3 + 0];
    const float ay = base[i0 * 3 + 1], aY = base[i1 * 3 + 1];
    const float az = base[i0 * 3 + 2], aZ = base[i1 * 3 + 2];
    const ull nx2 = pk(ax, aX);
    const ull ny2 = pk(ay, aY);
    const ull nz2 = pk(az, aZ);

    const ull k7 = pk(KC7, KC7), k6 = pk(KC6, KC6), k5 = pk(KC5, KC5);
    const ull k4 = pk(KC4, KC4), k3 = pk(KC3, KC3), k2 = pk(KC2, KC2);
    const ull k1 = pk(KC1, KC1), k0 = pk(KC0, KC0);
    const ull kL = pk(KLPI2, KLPI2);

    ull accA = pk(0.0f, 0.0f);
    ull accB = pk(0.0f, 0.0f);

    #pragma unroll 4
    for (int jj = 0; jj < JHALF; jj++) {
        const ull sx = sdx[jj];
        const ull sy = sdy[jj];
        const ull sz = sdz[jj];

        // packed dot for both rows against the same j
        ull d2 = fma2(nx2, sx, fma2(ny2, sy, mul2(nz2, sz)));

        float x0, x1; upk(d2, x0, x1);
        x0 = fminf(1.0f, fmaxf(-1.0f, x0));
        x1 = fminf(1.0f, fmaxf(-1.0f, x1));
        const float t0 = fabsf(x0), t1 = fabsf(x1);
        const float s0 = sqrt_apx(1.0f - t0);
        const float s1 = sqrt_apx(1.0f - t1);

        const ull t2 = pk(t0, t1);
        ull P = fma2(k7, t2, k6);
        P = fma2(P, t2, k5);  P = fma2(P, t2, k4);
        P = fma2(P, t2, k3);  P = fma2(P, t2, k2);
        P = fma2(P, t2, k1);  P = fma2(P, t2, k0);

        const ull r2 = fma2(pk(s0, s1), P, kL);
        float r0, r1; upk(r2, r0, r1);
        const float e0 = fmaf(sgn1(x0), r0, -KLPI2);
        const float e1 = fmaf(sgn1(x1), r1, -KLPI2);
        const ull w2 = pk(ex2_apx(e0), ex2_apx(e1));

        if (jj & 1) accB = add2(accB, w2);
        else        accA = add2(accA, w2);
    }

    ull acc = add2(accA, accB);
    float wlo, whi; upk(acc, wlo, whi);

    // subtract the self term for the row whose index falls in this j-half.
    // Same op chain as the loop -> exact cancellation of the j==i contribution.
    if (h == 0) {
        const float d = fmaf(ax, ax, fmaf(ay, ay, az * az));
        wlo -= wfun(d);
    } else {
        const float d = fmaf(aX, aX, fmaf(aY, aY, aZ * aZ));
        whi -= wfun(d);
    }

    g_wsum[h][b * NN + i0] = wlo;
    g_wsum[h][b * NN + i1] = whi;
}

// ---------------------------------------------------------------------------
// Pass 2: out[b] = normalize( sum_i w[b,i] * n_i )
// (global max division cancels under the final normalization — skipped)
// ---------------------------------------------------------------------------
__global__ __launch_bounds__(NN) void reduce_kernel(const float* __restrict__ normals,
                                                    float* __restrict__ out) {
    const int b = blockIdx.x;
    const int i = threadIdx.x;
    const float* base = normals + (size_t)b * NN * 3;

    const int idx = b * NN + i;
    const float w = g_wsum[0][idx] + g_wsum[1][idx];
    float px = w * base[i * 3 + 0];
    float py = w * base[i * 3 + 1];
    float pz = w * base[i * 3 + 2];

    #pragma unroll
    for (int off = 16; off > 0; off >>= 1) {
        px += __shfl_down_sync(0xFFFFFFFFu, px, off);
        py += __shfl_down_sync(0xFFFFFFFFu, py, off);
        pz += __shfl_down_sync(0xFFFFFFFFu, pz, off);
    }

    __shared__ float rx[16], ry[16], rz[16];
    const int warp = i >> 5;
    const int lane = i & 31;
    if (lane == 0) { rx[warp] = px; ry[warp] = py; rz[warp] = pz; }
    __syncthreads();

    if (warp == 0) {
        float qx = (lane < 16) ? rx[lane] : 0.f;
        float qy = (lane < 16) ? ry[lane] : 0.f;
        float qz = (lane < 16) ? rz[lane] : 0.f;
        #pragma unroll
        for (int off = 8; off > 0; off >>= 1) {
            qx += __shfl_down_sync(0xFFFFFFFFu, qx, off);
            qy += __shfl_down_sync(0xFFFFFFFFu, qy, off);
            qz += __shfl_down_sync(0xFFFFFFFFu, qz, off);
        }
        if (lane == 0) {
            const float s2 = fmaf(qx, qx, fmaf(qy, qy, qz * qz));
            const float inv = rsqrtf(fmaxf(s2, 1e-20f));
            out[b * 3 + 0] = qx * inv;
            out[b * 3 + 1] = qy * inv;
            out[b * 3 + 2] = qz * inv;
        }
    }
}

extern "C" void kernel_launch(void* const* d_in, const int* in_sizes, int n_in,
                              void* d_out, int out_size) {
    const float* normals = (const float*)d_in[0];   // [512,512,3] f32
    // d_in[1] = weights — unused by the reference math
    float* out = (float*)d_out;                     // [512,3] f32

    pair_kernel<<<dim3(BB, 2), TPB>>>(normals);
    reduce_kernel<<<BB, NN>>>(normals, out);
}